// round 8
// baseline (speedup 1.0000x reference)
#include <cuda_runtime.h>
#include <cuda_fp16.h>
#include <cstdint>

#define NN 100000      // input nodes
#define MM 100000      // output nodes
#define NNZ_C 3200000  // edges (divisible by 32)
#define BB 32          // batch

// Scratch
__device__ __half g_xth[NN * BB];  // x transposed (N, 32) in fp16, 6.4 MB
__device__ float  g_yt[MM * BB];   // y_t[m][b] accumulator, 12.8 MB

// ---------------------------------------------------------------------------
// Kernel 1: zero the accumulator (float4 grid-stride)
// ---------------------------------------------------------------------------
__global__ void zero_yt_kernel() {
    float4* p = reinterpret_cast<float4*>(g_yt);
    const int total = (MM * BB) / 4;
    for (int i = blockIdx.x * blockDim.x + threadIdx.x; i < total;
         i += gridDim.x * blockDim.x) {
        p[i] = make_float4(0.f, 0.f, 0.f, 0.f);
    }
}

// ---------------------------------------------------------------------------
// Kernel 2: transpose x (B, N) -> x_t (N, B) in fp16.
// 256 threads, 128-n x 32-b tile, float4 reads, 8B (4xhalf) writes.
// ---------------------------------------------------------------------------
__global__ void transpose_in_kernel(const float* __restrict__ x) {
    __shared__ float tile[128][33];
    int n0 = blockIdx.x * 128;
    int t = threadIdx.x;
#pragma unroll
    for (int i = 0; i < 4; i++) {
        int idx = i * 256 + t;      // 0..1023
        int b = idx >> 5;           // batch row 0..31
        int q = idx & 31;           // float4 index along n
        int n = n0 + q * 4;
        if (n + 3 < NN) {
            float4 xv = __ldg((const float4*)(x + b * NN + n));
            tile[q * 4 + 0][b] = xv.x;
            tile[q * 4 + 1][b] = xv.y;
            tile[q * 4 + 2][b] = xv.z;
            tile[q * 4 + 3][b] = xv.w;
        } else {
#pragma unroll
            for (int j = 0; j < 4; j++)
                if (n + j < NN) tile[q * 4 + j][b] = x[b * NN + n + j];
        }
    }
    __syncthreads();
#pragma unroll
    for (int i = 0; i < 4; i++) {
        int idx = i * 256 + t;
        int nloc = idx >> 3;        // 0..127
        int b4 = idx & 7;
        int n = n0 + nloc;
        if (n < NN) {
            __half2 h0 = __floats2half2_rn(tile[nloc][b4 * 4 + 0],
                                           tile[nloc][b4 * 4 + 1]);
            __half2 h1 = __floats2half2_rn(tile[nloc][b4 * 4 + 2],
                                           tile[nloc][b4 * 4 + 3]);
            uint2 o;
            o.x = *(const unsigned int*)&h0;
            o.y = *(const unsigned int*)&h1;
            *(uint2*)(g_xth + n * BB + b4 * 4) = o;
        }
    }
}

// ---------------------------------------------------------------------------
// Kernel 3: edge scatter. Each warp owns 32 edges (coalesced edge loads),
// processes 4 edges at a time: 8 lanes per edge. Gather = 64B fp16 row,
// scatter = red.global.add.v4.f32 (f32 accumulation).
// ---------------------------------------------------------------------------
__global__ void __launch_bounds__(256) edge_kernel(
        const int* __restrict__ src,
        const int* __restrict__ dst,
        const float* __restrict__ vals) {
    int gtid = blockIdx.x * blockDim.x + threadIdx.x;
    int warp_id = gtid >> 5;
    int lane = threadIdx.x & 31;

    int e = warp_id * 32 + lane;
    int   s = __ldg(&src[e]);
    int   d = __ldg(&dst[e]);
    float v = __ldg(&vals[e]);

    int seg = lane & 7;   // which 4-element slice of the 32-float batch row
    int sub = lane >> 3;  // which of 4 concurrent edges

    const uint2* xt2 = reinterpret_cast<const uint2*>(g_xth);  // 8B = 4 halves

#pragma unroll
    for (int j = 0; j < 8; j++) {
        int eidx = j * 4 + sub;
        int   se = __shfl_sync(0xffffffffu, s, eidx);
        int   de = __shfl_sync(0xffffffffu, d, eidx);
        float ve = __shfl_sync(0xffffffffu, v, eidx);
        uint2 xv = __ldg(&xt2[se * 8 + seg]);
        __half2 h0 = *(const __half2*)&xv.x;
        __half2 h1 = *(const __half2*)&xv.y;
        float2 f0 = __half22float2(h0);
        float2 f1 = __half22float2(h1);
        float cx = f0.x * ve, cy = f0.y * ve, cz = f1.x * ve, cw = f1.y * ve;
        float* p = g_yt + de * BB + seg * 4;
        asm volatile(
            "red.global.add.v4.f32 [%0], {%1, %2, %3, %4};"
            :: "l"(p), "f"(cx), "f"(cy), "f"(cz), "f"(cw)
            : "memory");
    }
}

// ---------------------------------------------------------------------------
// Kernel 4: out (B, M) = transpose(y_t (M, B)) + bias.
// Conflict-free both phases: tile[b][m_local] with 129 pitch.
// Phase 1: float4 reads of y_t (coalesced), bias fused.
// Phase 2: scalar stores, 32 consecutive m per warp (coalesced 128B).
// ---------------------------------------------------------------------------
__global__ void transpose_out_kernel(float* __restrict__ out,
                                     const float* __restrict__ bias) {
    __shared__ float tile[32][129];   // [b][m_local]
    int m0 = blockIdx.x * 128;
    int t = threadIdx.x;
#pragma unroll
    for (int i = 0; i < 4; i++) {
        int idx = i * 256 + t;      // 0..1023
        int mloc = idx >> 3;        // 0..127
        int b4 = idx & 7;
        int m = m0 + mloc;
        if (m < MM) {
            float4 yv = *(const float4*)(g_yt + m * BB + b4 * 4);
            float bi = __ldg(&bias[m]);
            // banks: (4*b4 + j + mloc) % 32 -> distinct within warp
            tile[b4 * 4 + 0][mloc] = yv.x + bi;
            tile[b4 * 4 + 1][mloc] = yv.y + bi;
            tile[b4 * 4 + 2][mloc] = yv.z + bi;
            tile[b4 * 4 + 3][mloc] = yv.w + bi;
        }
    }
    __syncthreads();
#pragma unroll
    for (int i = 0; i < 16; i++) {
        int idx = i * 256 + t;      // 0..4095
        int b  = idx >> 7;          // 0..31
        int ml = idx & 127;         // 0..127, consecutive within warp
        int m = m0 + ml;
        if (m < MM)
            out[b * MM + m] = tile[b][ml];   // banks (b+ml)%32 distinct
    }
}

// ---------------------------------------------------------------------------
extern "C" void kernel_launch(void* const* d_in, const int* in_sizes, int n_in,
                              void* d_out, int out_size) {
    const float* x       = (const float*)d_in[0];   // (B, N, 1)
    const int*   indices = (const int*)d_in[1];     // (2, NNZ)
    const float* vals    = (const float*)d_in[2];   // (NNZ,)
    const float* bias    = (const float*)d_in[3];   // (M, 1)
    float* out = (float*)d_out;                     // (B, M, 1)

    const int* src = indices;
    const int* dst = indices + NNZ_C;

    zero_yt_kernel<<<1600, 256>>>();
    transpose_in_kernel<<<(NN + 127) / 128, 256>>>(x);
    edge_kernel<<<NNZ_C / 256, 256>>>(src, dst, vals);
    transpose_out_kernel<<<(MM + 127) / 128, 256>>>(out, bias);
}